// round 1
// baseline (speedup 1.0000x reference)
#include <cuda_runtime.h>
#include <cuda_bf16.h>
#include <math.h>

#define N_NODES 100000
#define D 128
#define RREL 3
#define E_EDGES 600000

// Scratch: static device globals (no allocation allowed).
__device__ float g_M[(size_t)N_NODES * D];       // per-relation GEMM output (reused)
__device__ float g_acc[(size_t)N_NODES * D];     // scatter accumulator
__device__ float g_deg[(size_t)2 * RREL * N_NODES]; // [2r]=deg_out_r, [2r+1]=deg_in_r

// ---------------------------------------------------------------------------
// Zero accumulator + degree arrays
// ---------------------------------------------------------------------------
__global__ __launch_bounds__(256) void zero_kernel() {
    const int na = (N_NODES * D) / 4;          // float4 count for acc
    const int nd = (2 * RREL * N_NODES) / 4;   // float4 count for deg
    int i = blockIdx.x * 256 + threadIdx.x;
    float4 z = make_float4(0.f, 0.f, 0.f, 0.f);
    if (i < na) {
        ((float4*)g_acc)[i] = z;
    } else {
        int j = i - na;
        if (j < nd) ((float4*)g_deg)[j] = z;
    }
}

// ---------------------------------------------------------------------------
// Degree counting: grid.y = relation
// ---------------------------------------------------------------------------
__global__ __launch_bounds__(256) void degree_kernel(
    const int* __restrict__ s0, const int* __restrict__ d0,
    const int* __restrict__ s1, const int* __restrict__ d1,
    const int* __restrict__ s2, const int* __restrict__ d2)
{
    int e = blockIdx.x * 256 + threadIdx.x;
    if (e >= E_EDGES) return;
    int r = blockIdx.y;
    const int* sp = (r == 0) ? s0 : ((r == 1) ? s1 : s2);
    const int* dp = (r == 0) ? d0 : ((r == 1) ? d1 : d2);
    atomicAdd(&g_deg[(size_t)(2 * r) * N_NODES + sp[e]], 1.0f);
    atomicAdd(&g_deg[(size_t)(2 * r + 1) * N_NODES + dp[e]], 1.0f);
}

// ---------------------------------------------------------------------------
// GEMM: M = X @ W   (X: [n,128] row-major, W: [128,128] row-major)
// 128x128 block tile, 256 threads, 8x8 register tile, K chunks of 32.
// ---------------------------------------------------------------------------
#define BM 128
#define BN 128
#define BK 32
#define TM 8
#define TN 8

__global__ __launch_bounds__(256) void gemm_kernel(
    const float* __restrict__ X, const float* __restrict__ W, int n)
{
    __shared__ float As[BK][BM + 4];  // As[k][m] (transposed X tile)
    __shared__ float Bs[BK][BN + 4];  // Bs[k][n]

    const int row0 = blockIdx.x * BM;
    const int tid = threadIdx.x;
    const int tx = tid & 15;          // 0..15 -> 8 output cols each
    const int ty = tid >> 4;          // 0..15 -> 8 output rows each

    float acc[TM][TN];
#pragma unroll
    for (int i = 0; i < TM; i++)
#pragma unroll
        for (int j = 0; j < TN; j++) acc[i][j] = 0.f;

    for (int kc = 0; kc < D; kc += BK) {
        // Load A tile (128 rows x 32 k) transposed into As[k][m]
#pragma unroll
        for (int i = 0; i < 4; i++) {
            int f = tid + i * 256;        // float4 index, 1024 total
            int m = f >> 3;               // 0..127
            int kq = (f & 7) * 4;         // 0,4,...,28
            int grow = row0 + m;
            float4 v = make_float4(0.f, 0.f, 0.f, 0.f);
            if (grow < n)
                v = *(const float4*)(X + (size_t)grow * D + kc + kq);
            As[kq + 0][m] = v.x;
            As[kq + 1][m] = v.y;
            As[kq + 2][m] = v.z;
            As[kq + 3][m] = v.w;
        }
        // Load B tile (32 k x 128 cols)
#pragma unroll
        for (int i = 0; i < 4; i++) {
            int f = tid + i * 256;
            int k = f >> 5;               // 0..31
            int nn = (f & 31) * 4;        // 0..124
            float4 v = *(const float4*)(W + (size_t)(kc + k) * D + nn);
            *(float4*)&Bs[k][nn] = v;
        }
        __syncthreads();

#pragma unroll
        for (int k = 0; k < BK; k++) {
            float a[TM], b[TN];
#pragma unroll
            for (int i = 0; i < TM; i++) a[i] = As[k][ty * TM + i];
#pragma unroll
            for (int j = 0; j < TN; j++) b[j] = Bs[k][tx * TN + j];
#pragma unroll
            for (int i = 0; i < TM; i++)
#pragma unroll
                for (int j = 0; j < TN; j++)
                    acc[i][j] = fmaf(a[i], b[j], acc[i][j]);
        }
        __syncthreads();
    }

#pragma unroll
    for (int i = 0; i < TM; i++) {
        int grow = row0 + ty * TM + i;
        if (grow < n) {
#pragma unroll
            for (int j = 0; j < TN; j += 4) {
                float4 v = make_float4(acc[i][j], acc[i][j + 1],
                                       acc[i][j + 2], acc[i][j + 3]);
                *(float4*)(g_M + (size_t)grow * D + tx * TN + j) = v;
            }
        }
    }
}

// ---------------------------------------------------------------------------
// Scatter: acc[dst] += rsqrt(deg_out[src]) * rsqrt(deg_in[dst]) * M[src]
// One warp per edge, 128-bit vector atomics (sm_90+).
// ---------------------------------------------------------------------------
__global__ __launch_bounds__(256) void scatter_kernel(
    const int* __restrict__ src, const int* __restrict__ dst, int r)
{
    int w = (blockIdx.x * 256 + threadIdx.x) >> 5;
    if (w >= E_EDGES) return;
    int lane = threadIdx.x & 31;

    int s = __ldg(src + w);
    int d = __ldg(dst + w);
    float dout = g_deg[(size_t)(2 * r) * N_NODES + s];
    float din  = g_deg[(size_t)(2 * r + 1) * N_NODES + d];
    float c = rsqrtf(fmaxf(dout, 1.0f)) * rsqrtf(fmaxf(din, 1.0f));

    float4 v = *(const float4*)(g_M + (size_t)s * D + lane * 4);
    v.x *= c; v.y *= c; v.z *= c; v.w *= c;

    atomicAdd((float4*)(g_acc + (size_t)d * D + lane * 4), v);
}

// ---------------------------------------------------------------------------
// Epilogue: out = relu(acc + b0 + b1 + b2)
// ---------------------------------------------------------------------------
__global__ __launch_bounds__(256) void epilogue_kernel(
    const float* __restrict__ b0, const float* __restrict__ b1,
    const float* __restrict__ b2, float* __restrict__ out)
{
    int i = blockIdx.x * 256 + threadIdx.x;   // float4 index
    const int total4 = (N_NODES * D) / 4;
    if (i >= total4) return;
    int col = (i & 31) * 4;                   // column of first component
    float4 a = ((const float4*)g_acc)[i];
    float4 b;
    b.x = b0[col + 0] + b1[col + 0] + b2[col + 0];
    b.y = b0[col + 1] + b1[col + 1] + b2[col + 1];
    b.z = b0[col + 2] + b1[col + 2] + b2[col + 2];
    b.w = b0[col + 3] + b1[col + 3] + b2[col + 3];
    float4 o;
    o.x = fmaxf(a.x + b.x, 0.f);
    o.y = fmaxf(a.y + b.y, 0.f);
    o.z = fmaxf(a.z + b.z, 0.f);
    o.w = fmaxf(a.w + b.w, 0.f);
    ((float4*)out)[i] = o;
}

// ---------------------------------------------------------------------------
// Launcher: classify inputs by element count (robust to metadata ordering).
// ---------------------------------------------------------------------------
extern "C" void kernel_launch(void* const* d_in, const int* in_sizes, int n_in,
                              void* d_out, int out_size)
{
    const float* x = nullptr;
    const float* Wp[RREL] = {nullptr, nullptr, nullptr};
    const float* bp[RREL] = {nullptr, nullptr, nullptr};
    const int*   ep[2 * RREL] = {nullptr};  // src0,dst0,src1,dst1,src2,dst2
    int wi = 0, bi = 0, ei = 0;

    for (int i = 0; i < n_in; i++) {
        int sz = in_sizes[i];
        if (sz == N_NODES * D)      x = (const float*)d_in[i];
        else if (sz == D * D)       { if (wi < RREL) Wp[wi++] = (const float*)d_in[i]; }
        else if (sz == D)           { if (bi < RREL) bp[bi++] = (const float*)d_in[i]; }
        else if (sz == E_EDGES)     { if (ei < 2 * RREL) ep[ei++] = (const int*)d_in[i]; }
    }

    float* out = (float*)d_out;

    // 1. zero acc + degree arrays
    {
        int total = (N_NODES * D) / 4 + (2 * RREL * N_NODES) / 4;
        int blocks = (total + 255) / 256;
        zero_kernel<<<blocks, 256>>>();
    }

    // 2. degrees (all relations)
    {
        dim3 grid((E_EDGES + 255) / 256, RREL);
        degree_kernel<<<grid, 256>>>(ep[0], ep[1], ep[2], ep[3], ep[4], ep[5]);
    }

    // 3. per relation: GEMM then scatter (keeps M_r + acc hot in L2)
    const int gemm_blocks = (N_NODES + BM - 1) / BM;
    const int scat_blocks = ((long long)E_EDGES * 32 + 255) / 256;
    for (int r = 0; r < RREL; r++) {
        gemm_kernel<<<gemm_blocks, 256>>>(x, Wp[r], N_NODES);
        scatter_kernel<<<scat_blocks, 256>>>(ep[2 * r], ep[2 * r + 1], r);
    }

    // 4. epilogue: bias + relu
    {
        int total4 = (N_NODES * D) / 4;
        epilogue_kernel<<<(total4 + 255) / 256, 256>>>(bp[0], bp[1], bp[2], out);
    }
}